// round 12
// baseline (speedup 1.0000x reference)
#include <cuda_runtime.h>

#define BATCH 4096
#define SEQT  256
#define DIN   32
#define HID   64
#define GATES 256
#define BT    32
#define NTHR  256
#define NCTA  128
#define STD   68          // floats per dup k-row (64 data + 4 skew/pad)
#define HST   33          // final-h scratch stride

typedef unsigned long long u64;

// ---- gate-quad weight layout W[k][u2][g][upar]: n = g*64 + u2*2 + up (R9-proven) ----
__device__ __align__(16) float g_W0q[HID * GATES];     // Whh0 quad (per-step LDG)
__device__ __align__(16) float g_Wx0q[DIN * GATES];    // Wih0 quad (per-step LDG)
__device__ __align__(16) float g_W1q[2 * HID * GATES]; // [Wih1; Whh1] quad (-> smem)
__device__ __align__(16) float g_b0q[GATES];
__device__ __align__(16) float g_b1q[GATES];

__global__ void prep_kernel(const float* __restrict__ Wih0, const float* __restrict__ Whh0,
                            const float* __restrict__ bih0, const float* __restrict__ bhh0,
                            const float* __restrict__ Wih1, const float* __restrict__ Whh1,
                            const float* __restrict__ bih1, const float* __restrict__ bhh1)
{
    int idx = blockIdx.x * blockDim.x + threadIdx.x;
    int stride = gridDim.x * blockDim.x;
    for (int j = idx; j < HID * GATES; j += stride) {
        int k = j / GATES, r = j % GATES;
        int n = ((r >> 1) & 3) * HID + (r >> 3) * 2 + (r & 1);
        g_W0q[j] = Whh0[n * HID + k];
    }
    for (int j = idx; j < DIN * GATES; j += stride) {
        int k = j / GATES, r = j % GATES;
        int n = ((r >> 1) & 3) * HID + (r >> 3) * 2 + (r & 1);
        g_Wx0q[j] = Wih0[n * DIN + k];
    }
    for (int j = idx; j < 2 * HID * GATES; j += stride) {
        int k = j / GATES, r = j % GATES;
        int n = ((r >> 1) & 3) * HID + (r >> 3) * 2 + (r & 1);
        g_W1q[j] = (k < HID) ? Wih1[n * HID + k] : Whh1[n * HID + (k - HID)];
    }
    for (int r = idx; r < GATES; r += stride) {
        int n = ((r >> 1) & 3) * HID + (r >> 3) * 2 + (r & 1);
        g_b0q[r] = bih0[n] + bhh0[n];
        g_b1q[r] = bih1[n] + bhh1[n];
    }
}

// ---- packed f32x2 helpers ----
__device__ __forceinline__ u64 fma2(u64 a, u64 b, u64 c) {
    u64 d;
    asm("fma.rn.f32x2 %0, %1, %2, %3;" : "=l"(d) : "l"(a), "l"(b), "l"(c));
    return d;
}
__device__ __forceinline__ float2 unpack2(u64 v) {
    float2 f;
    asm("mov.b64 {%0, %1}, %2;" : "=f"(f.x), "=f"(f.y) : "l"(v));
    return f;
}

// ---- fast activations (MUFU EX2/RCP, proven ~2.5e-7 end-to-end) ----
__device__ __forceinline__ float fast_ex2(float x) {
    float y; asm("ex2.approx.f32 %0, %1;" : "=f"(y) : "f"(x)); return y;
}
__device__ __forceinline__ float fast_rcp(float x) {
    float y; asm("rcp.approx.f32 %0, %1;" : "=f"(y) : "f"(x)); return y;
}
__device__ __forceinline__ float sigf(float x) {
    return fast_rcp(1.0f + fast_ex2(-1.4426950408889634f * x));
}
__device__ __forceinline__ float tanhf_fast(float x) {
    x = fminf(fmaxf(x, -15.0f), 15.0f);
    float e = fast_ex2(-2.8853900817779268f * x);
    return (1.0f - e) * fast_rcp(1.0f + e);
}

// GEMM fragment on DUPLICATED acts: per k: 2 LDS.128 acts (4 dup rows) + 2 x.128 weights,
// 16 FFMA2. acc[r][g] = f32x2 over (u0,u0+1), gate g, row m0+r. ZERO MOVs.
template <bool GW, int K>
__device__ __forceinline__ void gemm_dup(const float* __restrict__ aT,
                                         const float* __restrict__ Wq,
                                         int aoff, int w8, u64 acc[4][4])
{
#pragma unroll 8
    for (int k = 0; k < K; k++) {
        ulonglong2 a01 = *(const ulonglong2*)(aT + k * STD + aoff);
        ulonglong2 a23 = *(const ulonglong2*)(aT + k * STD + aoff + 4);
        const float* wp = Wq + k * GATES + w8;
        ulonglong2 wv0, wv1;
        if (GW) {
            wv0 = __ldg((const ulonglong2*)wp);
            wv1 = __ldg((const ulonglong2*)(wp + 4));
        } else {
            wv0 = *(const ulonglong2*)wp;
            wv1 = *(const ulonglong2*)(wp + 4);
        }
        acc[0][0] = fma2(a01.x, wv0.x, acc[0][0]);
        acc[0][1] = fma2(a01.x, wv0.y, acc[0][1]);
        acc[0][2] = fma2(a01.x, wv1.x, acc[0][2]);
        acc[0][3] = fma2(a01.x, wv1.y, acc[0][3]);
        acc[1][0] = fma2(a01.y, wv0.x, acc[1][0]);
        acc[1][1] = fma2(a01.y, wv0.y, acc[1][1]);
        acc[1][2] = fma2(a01.y, wv1.x, acc[1][2]);
        acc[1][3] = fma2(a01.y, wv1.y, acc[1][3]);
        acc[2][0] = fma2(a23.x, wv0.x, acc[2][0]);
        acc[2][1] = fma2(a23.x, wv0.y, acc[2][1]);
        acc[2][2] = fma2(a23.x, wv1.x, acc[2][2]);
        acc[2][3] = fma2(a23.x, wv1.y, acc[2][3]);
        acc[3][0] = fma2(a23.y, wv0.x, acc[3][0]);
        acc[3][1] = fma2(a23.y, wv0.y, acc[3][1]);
        acc[3][2] = fma2(a23.y, wv1.x, acc[3][2]);
        acc[3][3] = fma2(a23.y, wv1.y, acc[3][3]);
    }
}

__device__ __forceinline__ void acc_init(const float* __restrict__ sB, int w8, u64 acc[4][4])
{
    ulonglong2 b0 = *(const ulonglong2*)(sB + w8);
    ulonglong2 b1 = *(const ulonglong2*)(sB + w8 + 4);
#pragma unroll
    for (int r = 0; r < 4; r++) {
        acc[r][0] = b0.x; acc[r][1] = b0.y; acc[r][2] = b1.x; acc[r][3] = b1.y;
    }
}

// compute activations for 4 rows x 2 cells; optionally store dup-format h
__device__ __forceinline__ void lstm_gates(const u64 acc[4][4], float c[4][2], float h[4][2])
{
#pragma unroll
    for (int r = 0; r < 4; r++) {
        float2 pi = unpack2(acc[r][0]);
        float2 pf = unpack2(acc[r][1]);
        float2 pg = unpack2(acc[r][2]);
        float2 po = unpack2(acc[r][3]);
        {
            float iv = sigf(pi.x), fv = sigf(pf.x), gv = tanhf_fast(pg.x), ov = sigf(po.x);
            float cc = fv * c[r][0] + iv * gv;
            c[r][0] = cc;
            h[r][0] = ov * tanhf_fast(cc);
        }
        {
            float iv = sigf(pi.y), fv = sigf(pf.y), gv = tanhf_fast(pg.y), ov = sigf(po.y);
            float cc = fv * c[r][1] + iv * gv;
            c[r][1] = cc;
            h[r][1] = ov * tanhf_fast(cc);
        }
    }
}

__device__ __forceinline__ void store_h_dup(const float h[4][2], float* __restrict__ dst,
                                            int aoff, int u0)
{
    *(float4*)(dst + (u0 + 0) * STD + aoff)     = make_float4(h[0][0], h[0][0], h[1][0], h[1][0]);
    *(float4*)(dst + (u0 + 0) * STD + aoff + 4) = make_float4(h[2][0], h[2][0], h[3][0], h[3][0]);
    *(float4*)(dst + (u0 + 1) * STD + aoff)     = make_float4(h[0][1], h[0][1], h[1][1], h[1][1]);
    *(float4*)(dst + (u0 + 1) * STD + aoff + 4) = make_float4(h[2][1], h[2][1], h[3][1], h[3][1]);
}

// Buffer sub-offsets (floats): h0 k=0..63, h1 k=64..127, x k=128..159
#define H0OFF  0
#define H1OFF  (64 * STD)
#define XOFF   (128 * STD)
#define BUFSZ  (160 * STD)

// Shared layout (floats)
#define OFF_W1   0
#define OFF_B0   (OFF_W1 + 2 * HID * GATES)   // 32768
#define OFF_B1   (OFF_B0 + GATES)
#define OFF_BUF0 (OFF_B1 + GATES)             // 33280
#define OFF_BUF1 (OFF_BUF0 + BUFSZ)
#define SMEM_FLOATS (OFF_BUF1 + BUFSZ)        // 55040 floats = 220160 B

__global__ void __launch_bounds__(NTHR, 1)
lstm_fused(const float* __restrict__ x,
           const float* __restrict__ W1h, const float* __restrict__ b1h,
           const float* __restrict__ W2h, const float* __restrict__ b2h,
           float* __restrict__ out)
{
    extern __shared__ float sm[];
    float* sW1  = sm + OFF_W1;     // [Wih1;Whh1] quad
    float* sB0  = sm + OFF_B0;
    float* sB1  = sm + OFF_B1;
    float* buf0 = sm + OFF_BUF0;
    float* buf1 = sm + OFF_BUF1;

    const int tid = threadIdx.x;
    const int b0  = blockIdx.x * BT;

    // stage W1 + biases; zero both act buffers
    for (int i = tid; i < 2 * HID * GATES / 4; i += NTHR)
        ((float4*)sW1)[i] = ((const float4*)g_W1q)[i];
    if (tid < GATES) { sB0[tid] = g_b0q[tid]; sB1[tid] = g_b1q[tid]; }
    for (int i = tid; i < 2 * BUFSZ; i += NTHR) buf0[i] = 0.0f;  // buf0+buf1 contiguous

    // thread tile: rows m0..m0+3 (m0=gm*4), cells u0,u0+1 (quad block w8=gn*8)
    const int gm = tid & 7;
    const int gn = tid >> 3;
    const int m0 = gm * 4;
    const int u0 = gn * 2;
    const int w8 = gn * 8;
    const int aoff = gm * 8 + (gm >= 4 ? 4 : 0);   // dup act offset with bank skew

    float c0[4][2] = {{0,0},{0,0},{0,0},{0,0}};
    float c1[4][2] = {{0,0},{0,0},{0,0},{0,0}};
    u64 acc0[4][4], acc1[4][4];
    float h[4][2];

    // x staging: thread -> (row xm, float4 d-chunk xd); dup-stored
    const int xm = tid >> 3;
    const int xd = tid & 7;
    const int xoff = 2 * xm + (xm >= 16 ? 4 : 0);
    const float* xrow = x + (size_t)(b0 + xm) * SEQT * DIN + xd * 4;

    // prologue: stage x(0) dup into buf1.X
    float4 xv = *(const float4*)(xrow);
    {
        float* xb = buf1 + XOFF;
        *(float2*)(xb + (4 * xd + 0) * STD + xoff) = make_float2(xv.x, xv.x);
        *(float2*)(xb + (4 * xd + 1) * STD + xoff) = make_float2(xv.y, xv.y);
        *(float2*)(xb + (4 * xd + 2) * STD + xoff) = make_float2(xv.z, xv.z);
        *(float2*)(xb + (4 * xd + 3) * STD + xoff) = make_float2(xv.w, xv.w);
    }
    __syncthreads();

    // acc0(0) = b0 + Wih0*x(0)   (h0(-1)=0 contribution skipped exactly)
    acc_init(sB0, w8, acc0);
    gemm_dup<true, DIN>(buf1 + XOFF, g_Wx0q, aoff, w8, acc0);
    xv = *(const float4*)(xrow + DIN);   // x(1)
    __syncthreads();                     // buf1.X readers done before U(0) rewrites

    float* wb = buf1;   // write/read buffer for iteration t (swaps each step)
    float* ob = buf0;

    for (int t = 0; t < SEQT; t++) {
        // ---- phase U: update1(t-1), update0(t), stage x(t+1)  (writes wb)
        if (t) {
            lstm_gates(acc1, c1, h);
            store_h_dup(h, wb + H1OFF, aoff, u0);   // h1(t-1)
        }
        lstm_gates(acc0, c0, h);
        store_h_dup(h, wb + H0OFF, aoff, u0);       // h0(t)
        {
            float* xb = wb + XOFF;
            *(float2*)(xb + (4 * xd + 0) * STD + xoff) = make_float2(xv.x, xv.x);
            *(float2*)(xb + (4 * xd + 1) * STD + xoff) = make_float2(xv.y, xv.y);
            *(float2*)(xb + (4 * xd + 2) * STD + xoff) = make_float2(xv.z, xv.z);
            *(float2*)(xb + (4 * xd + 3) * STD + xoff) = make_float2(xv.w, xv.w);
            int tn = (t + 2 < SEQT) ? t + 2 : SEQT - 1;
            xv = *(const float4*)(xrow + (size_t)tn * DIN);
        }
        __syncthreads();   // THE single barrier per step

        // ---- phase G: gemm1(t) from smem W1; gemm0(t+1) from L2 weights (reads wb)
        acc_init(sB1, w8, acc1);
        gemm_dup<false, HID>(wb + H0OFF, sW1, aoff, w8, acc1);              // Wih1*h0(t)
        gemm_dup<false, HID>(wb + H1OFF, sW1 + HID * GATES, aoff, w8, acc1);// Whh1*h1(t-1)
        if (t + 1 < SEQT) {
            acc_init(sB0, w8, acc0);
            gemm_dup<true, DIN>(wb + XOFF, g_Wx0q, aoff, w8, acc0);  // Wih0*x(t+1)
            gemm_dup<true, HID>(wb + H0OFF, g_W0q, aoff, w8, acc0);  // Whh0*h0(t)
        }
        // swap buffers
        float* tmp = wb; wb = ob; ob = tmp;
    }

    // final update1(255) -> plain store into buf1 region (no readers left there)
    lstm_gates(acc1, c1, h);
    {
        float* hfin = buf1;
#pragma unroll
        for (int j = 0; j < 2; j++)
#pragma unroll
            for (int r = 0; r < 4; r++)
                hfin[(u0 + j) * HST + m0 + r] = h[r][j];
    }
    __syncthreads();

    // ---- head: out[m] = b2 + sum_n W2[n]*relu(b1[n] + sum_k h1(k,m) W1[n,k]) ----
    {
        const float* hfin = buf1;
        int m = tid >> 3;      // 0..31
        int q = tid & 7;       // 0..7
        float pm = 0.0f;
#pragma unroll
        for (int jj = 0; jj < 8; jj++) {
            int n = q * 8 + jj;
            float sv = b1h[n];
#pragma unroll 8
            for (int k = 0; k < HID; k++)
                sv += hfin[k * HST + m] * W1h[n * HID + k];
            pm += fmaxf(sv, 0.0f) * W2h[n];
        }
#pragma unroll
        for (int off = 4; off > 0; off >>= 1)
            pm += __shfl_down_sync(0xffffffffu, pm, off, 8);
        if (q == 0) out[b0 + m] = pm + b2h[0];
    }
}

extern "C" void kernel_launch(void* const* d_in, const int* in_sizes, int n_in,
                              void* d_out, int out_size)
{
    const float* x    = (const float*)d_in[0];
    const float* Wih0 = (const float*)d_in[1];
    const float* Whh0 = (const float*)d_in[2];
    const float* bih0 = (const float*)d_in[3];
    const float* bhh0 = (const float*)d_in[4];
    const float* Wih1 = (const float*)d_in[5];
    const float* Whh1 = (const float*)d_in[6];
    const float* bih1 = (const float*)d_in[7];
    const float* bhh1 = (const float*)d_in[8];
    const float* W1   = (const float*)d_in[9];
    const float* b1   = (const float*)d_in[10];
    const float* W2   = (const float*)d_in[11];
    const float* b2   = (const float*)d_in[12];

    prep_kernel<<<64, 256>>>(Wih0, Whh0, bih0, bhh0, Wih1, Whh1, bih1, bhh1);

    size_t smem_bytes = (size_t)SMEM_FLOATS * sizeof(float);   // 220160 B
    cudaFuncSetAttribute(lstm_fused,
                         cudaFuncAttributeMaxDynamicSharedMemorySize, (int)smem_bytes);
    lstm_fused<<<NCTA, NTHR, smem_bytes>>>(x, W1, b1, W2, b2, (float*)d_out);
}